// round 13
// baseline (speedup 1.0000x reference)
#include <cuda_runtime.h>
#include <cuda_fp16.h>
#include <cstdint>

#define NB 65536
#define NL 64
#define GRID_P 256           // interpolation grid resolution
#define NPTS (GRID_P + 1)    // 257 points per pair
#define NPAIR 100
#define SDG_RS 168           // digit staging row stride (floats), mod 32 = 8, 16B-aligned rows
#define SCAR_RS 36           // carry staging row stride (floats)

typedef unsigned long long ull;

// ---- device scratch (no allocations allowed) ----
// fp32 scratch: 16 floats/entry: [0..11] logits, [12..15] pad
__device__ __align__(128) float g_scratch[(size_t)NPAIR * NPTS * 16];
// compact table: 16 uints (64B)/entry:
//   uint j (0..11) = half2(val_j, val_j(k+1)-val_j(k))
//   uint 12 = fp32 u_next val (p*GRID_P), uint 13 = fp32 u_next delta, 14..15 pad
__device__ __align__(128) unsigned int g_tab16[(size_t)NPAIR * NPTS * 16];

// ---- bit-reinterpret helpers ----
__device__ __forceinline__ unsigned int h2_as_u32(__half2 h) {
    return *reinterpret_cast<unsigned int*>(&h);
}
__device__ __forceinline__ __half2 u32_as_h2(unsigned int u) {
    return *reinterpret_cast<__half2*>(&u);
}

// ---- f32x2 helpers ----
__device__ __forceinline__ ull pack2(float x, float y) {
    ull r; asm("mov.b64 %0, {%1,%2};" : "=l"(r) : "f"(x), "f"(y)); return r;
}
__device__ __forceinline__ void unpack2(ull a, float &x, float &y) {
    asm("mov.b64 {%0,%1}, %2;" : "=f"(x), "=f"(y) : "l"(a));
}
__device__ __forceinline__ void ffma2(ull &c, ull a, ull b) {
    asm("fma.rn.f32x2 %0, %1, %2, %0;" : "+l"(c) : "l"(a), "l"(b));
}
__device__ __forceinline__ ull add2(ull a, ull b) {
    ull r; asm("add.rn.f32x2 %0, %1, %2;" : "=l"(r) : "l"(a), "l"(b)); return r;
}
__device__ __forceinline__ ull fma2v(ull a, ull b, ull c) {
    ull r; asm("fma.rn.f32x2 %0, %1, %2, %3;" : "=l"(r) : "l"(a), "l"(b), "l"(c)); return r;
}

// ---- bulk smem->gmem copy helpers ----
__device__ __forceinline__ void bulk_s2g(void* dst, const void* smem_src, unsigned bytes) {
    unsigned s = (unsigned)__cvta_generic_to_shared(smem_src);
    asm volatile("cp.async.bulk.global.shared::cta.bulk_group [%0], [%1], %2;"
        :: "l"(dst), "r"(s), "r"(bytes) : "memory");
}
__device__ __forceinline__ void bulk_commit() {
    asm volatile("cp.async.bulk.commit_group;" ::: "memory");
}
__device__ __forceinline__ void bulk_wait_read0() {
    asm volatile("cp.async.bulk.wait_group.read 0;" ::: "memory");
}
__device__ __forceinline__ void bulk_wait0() {
    asm volatile("cp.async.bulk.wait_group 0;" ::: "memory");
}
__device__ __forceinline__ void fence_async_shared() {
    asm volatile("fence.proxy.async.shared::cta;" ::: "memory");
}

// ---- build fp32 scratch: 4 threads cooperate per (pair, gridpoint) entry ----
__global__ void __launch_bounds__(256) build_vals(
    const float* __restrict__ Ea, const float* __restrict__ Eb,
    const float* __restrict__ W1, const float* __restrict__ b1,
    const float* __restrict__ W2, const float* __restrict__ b2,
    const float* __restrict__ Wd, const float* __restrict__ bd,
    const float* __restrict__ Wc, const float* __restrict__ bc)
{
    __shared__ __align__(16) float sTa[660], sTb[660];
    __shared__ __align__(16) float sv[64];
    __shared__ __align__(16) float sW2p[2048];   // [j][i] transposed; (i,i+1) pairs contiguous
    __shared__ __align__(16) float sHd[384];     // [i][d]: 12 head weights per unit i
    __shared__ __align__(16) float sB2[32];
    __shared__ __align__(16) float sBdc[16];

    int tid = threadIdx.x;  // 256
    // fold embeddings + layer1 into per-digit tables (redundant per CTA, trivial)
    for (int n = tid; n < 640; n += 256) {
        int j = n & 63, d = n >> 6;
        float w16 = W1[j * 18 + 16];
        float sa = 0.f, sb = 0.f;
        #pragma unroll
        for (int k = 0; k < 8; k++) {
            sa += Ea[d * 8 + k] * W1[j * 18 + k];
            sb += Eb[d * 8 + k] * W1[j * 18 + 8 + k];
        }
        sTa[d * 66 + j] = b1[j] + w16 + sa;
        sTb[d * 66 + j] = sb;
    }
    if (tid < 64) sv[tid] = W1[tid * 18 + 17] - W1[tid * 18 + 16];
    for (int n = tid; n < 2048; n += 256) { int j = n >> 5, i = n & 31; sW2p[n] = W2[i * 64 + j]; }
    for (int n = tid; n < 384; n += 256) {
        int i = n / 12, d = n % 12;
        sHd[n] = (d < 10) ? Wd[d * 32 + i] : Wc[(d - 10) * 32 + i];
    }
    if (tid < 32) sB2[tid] = b2[tid];
    if (tid < 16) sBdc[tid] = (tid < 10) ? bd[tid] : (tid < 12 ? bc[tid - 10] : 0.f);
    __syncthreads();

    int idx = blockIdx.x * 64 + (tid >> 2);   // entry per quad
    int t = tid & 3;                          // quad lane
    if (idx >= NPAIR * NPTS) return;
    int pr = idx / NPTS;
    int k = idx - pr * NPTS;
    int a0 = pr / 10, b0 = pr - a0 * 10;
    float p = (float)k * (1.0f / (float)GRID_P);

    const float* ta = sTa + a0 * 66 + t * 16;
    const float* tb = sTb + b0 * 66 + t * 16;
    const float* svt = sv + t * 16;
    ull pp = pack2(p, p);

    // partial acc over this lane's 16 j's; lane 0 seeds biases
    ull acc[16];
    if (t == 0) {
        const ulonglong2* bp = (const ulonglong2*)sB2;
        #pragma unroll
        for (int q = 0; q < 8; q++) { ulonglong2 v2 = bp[q]; acc[2 * q] = v2.x; acc[2 * q + 1] = v2.y; }
    } else {
        #pragma unroll
        for (int i = 0; i < 16; i++) acc[i] = 0ull;
    }

    ull hh[16];
    #pragma unroll
    for (int jp = 0; jp < 8; jp++) {
        int j = jp * 2;
        ull s = fma2v(pp, *(const ull*)(svt + j),
                      add2(*(const ull*)(ta + j), *(const ull*)(tb + j)));
        float x, y; unpack2(s, x, y);
        x = fmaxf(x, 0.f); y = fmaxf(y, 0.f);
        hh[2 * jp] = pack2(x, x);
        hh[2 * jp + 1] = pack2(y, y);
    }
    #pragma unroll
    for (int jj = 0; jj < 16; jj++) {
        int j = t * 16 + jj;
        ull h = hh[jj];
        const ulonglong2* wp = (const ulonglong2*)(sW2p + j * 32);
        #pragma unroll
        for (int q = 0; q < 8; q++) {
            ulonglong2 w = wp[q];
            ffma2(acc[2 * q], h, w.x);
            ffma2(acc[2 * q + 1], h, w.y);
        }
    }

    // quad butterfly reduce -> full h2 (with relu) in every lane
    float h2[32];
    #pragma unroll
    for (int i = 0; i < 16; i++) {
        float x, y; unpack2(acc[i], x, y);
        x += __shfl_xor_sync(0xffffffffu, x, 1);
        y += __shfl_xor_sync(0xffffffffu, y, 1);
        x += __shfl_xor_sync(0xffffffffu, x, 2);
        y += __shfl_xor_sync(0xffffffffu, y, 2);
        h2[2 * i] = fmaxf(x, 0.f);
        h2[2 * i + 1] = fmaxf(y, 0.f);
    }

    // head split by output: lane t computes logits d = t, t+4, t+8
    float l0 = sBdc[t], l1 = sBdc[t + 4], l2 = sBdc[t + 8];
    #pragma unroll
    for (int i = 0; i < 32; i++) {
        float h = h2[i];
        const float* hw = sHd + i * 12 + t;
        l0 = fmaf(h, hw[0], l0);
        l1 = fmaf(h, hw[4], l1);
        l2 = fmaf(h, hw[8], l2);
    }

    float* o = g_scratch + (size_t)idx * 16;
    o[t] = l0; o[t + 4] = l1; o[t + 8] = l2;
}

// ---- finalize compact table: one thread per entry (computes p_next here) ----
__global__ void __launch_bounds__(256) finalize_tab() {
    int e = blockIdx.x * 256 + threadIdx.x;
    if (e >= NPAIR * NPTS) return;
    int pr = e / NPTS;
    int k = e - pr * NPTS;
    int en = (k < GRID_P) ? (e + 1) : e;      // neighbor (delta=0 at the last point)

    const float4* c0 = (const float4*)(g_scratch + (size_t)e * 16);
    const float4* c1 = (const float4*)(g_scratch + (size_t)en * 16);
    float4 v0 = c0[0], v1 = c0[1], v2 = c0[2];
    float4 n0 = c1[0], n1 = c1[1], n2 = c1[2];

    // u_next = p_next * GRID_P (pre-scaled recursion state)
    float pv = (float)GRID_P / (1.f + __expf(v2.z - v2.w));
    float pn = (float)GRID_P / (1.f + __expf(n2.z - n2.w));

    unsigned int* o = g_tab16 + (size_t)e * 16;
    uint4 w;
    w.x = h2_as_u32(__floats2half2_rn(v0.x, n0.x - v0.x));
    w.y = h2_as_u32(__floats2half2_rn(v0.y, n0.y - v0.y));
    w.z = h2_as_u32(__floats2half2_rn(v0.z, n0.z - v0.z));
    w.w = h2_as_u32(__floats2half2_rn(v0.w, n0.w - v0.w));
    ((uint4*)o)[0] = w;
    w.x = h2_as_u32(__floats2half2_rn(v1.x, n1.x - v1.x));
    w.y = h2_as_u32(__floats2half2_rn(v1.y, n1.y - v1.y));
    w.z = h2_as_u32(__floats2half2_rn(v1.z, n1.z - v1.z));
    w.w = h2_as_u32(__floats2half2_rn(v1.w, n1.w - v1.w));
    ((uint4*)o)[1] = w;
    w.x = h2_as_u32(__floats2half2_rn(v2.x, n2.x - v2.x));
    w.y = h2_as_u32(__floats2half2_rn(v2.y, n2.y - v2.y));
    w.z = h2_as_u32(__floats2half2_rn(v2.z, n2.z - v2.z));
    w.w = h2_as_u32(__floats2half2_rn(v2.w, n2.w - v2.w));
    ((uint4*)o)[2] = w;
    w.x = __float_as_uint(pv);
    w.y = __float_as_uint(pn - pv);
    w.z = 0u; w.w = 0u;
    ((uint4*)o)[3] = w;
}

// ---- main: 8 lanes/row, 32 rows/CTA, scaled-u recursion, bulk-copy output ----
__global__ void __launch_bounds__(256, 8) mlp_lookup(
    const int* __restrict__ aI, const int* __restrict__ bI, float* __restrict__ out)
{
    __shared__ __align__(16) unsigned char sdig[32 * 64];   // [row][t] pair index
    __shared__ __align__(16) float sdg[32 * SDG_RS];        // [row][tt*10+d] digit chunk buffer
    __shared__ __align__(16) float scar[32 * SCAR_RS];      // [row][tt*2+k] carry chunk buffer
    __shared__ int sflagA, sflagB;

    int tid = threadIdx.x;           // 256
    int lrow = tid >> 3;             // 0..31 (row within CTA)
    int q = tid & 7;                 // lane within 8-lane row group
    int lane = tid & 31;
    int rowbase = blockIdx.x * 32;

    // dtype sniff: int64 viewed as int32 has high words (odd indices) all zero
    if (tid < 32) {
        int v = aI[2 * tid + 1];
        unsigned m = __ballot_sync(0xffffffffu, v == 0);
        if (tid == 0) sflagA = (m == 0xffffffffu);
    } else if (tid < 64) {
        int l = tid - 32;
        int v = bI[2 * l + 1];
        unsigned m = __ballot_sync(0xffffffffu, v == 0);
        if (l == 0) sflagB = (m == 0xffffffffu);
    }
    __syncthreads();
    bool f64a = sflagA != 0, f64b = sflagB != 0;

    // load + transpose this CTA's digits into smem
    #pragma unroll
    for (int kk = 0; kk < 8; kk++) {
        int i = tid + kk * 256;      // 0..2047
        int r = i >> 6, t = i & 63;
        size_t idx = (size_t)(rowbase + r) * NL + t;
        int av = f64a ? aI[2 * idx] : aI[idx];
        int bv = f64b ? bI[2 * idx] : bI[idx];
        sdig[r * 64 + t] = (unsigned char)(av * 10 + bv);
    }
    __syncthreads();

    // per-thread store routing (loop-invariant): q 0-4 -> digits, q 5 -> carry
    float* digrow = sdg + lrow * SDG_RS;
    float* carrow = scar + lrow * SCAR_RS;
    bool doStore = (q < 6);
    float* pbase = (q < 5) ? (digrow + 2 * q) : carrow;
    int pstride = (q < 5) ? 10 : 2;
    int psrc = (lane & 24) | 6;      // lane holding u_next (q==6) in this 8-lane group

    // bulk-copy routing for this thread (tid < 64 issues one copy per chunk)
    float* bdst0 = 0; const float* bsrc = 0; unsigned bbytes = 0; int bstep = 0;
    float* outc_base = out + (size_t)NB * NL * 10;
    if (tid < 32) {
        bdst0 = out + (size_t)(rowbase + tid) * (NL * 10);
        bsrc = sdg + tid * SDG_RS;
        bbytes = 640; bstep = 160;
    } else if (tid < 64) {
        int r = tid - 32;
        bdst0 = outc_base + (size_t)(rowbase + r) * (NL * 2);
        bsrc = scar + r * SCAR_RS;
        bbytes = 128; bstep = 32;
    }

    const unsigned int* T = g_tab16;
    float u = 0.f;   // scaled recursion state u = p * GRID_P; t=0 carry = [1,0] <=> u = 0

    #pragma unroll 1
    for (int c = 0; c < 4; c++) {
        if (c > 0) {
            if (tid < 64) bulk_wait_read0();   // staging buffer free for reuse
            __syncthreads();
        }

        // 16 pair-bytes for this chunk in one LDS.128
        uint4 dw = *(const uint4*)(sdig + lrow * 64 + c * 16);

        #pragma unroll 1
        for (int tt4 = 0; tt4 < 4; tt4++) {
            unsigned w4 = (tt4 == 0) ? dw.x : (tt4 == 1) ? dw.y : (tt4 == 2) ? dw.z : dw.w;
            #pragma unroll
            for (int s = 0; s < 4; s++) {
                int tt = tt4 * 4 + s;
                int pr = (w4 >> (8 * s)) & 255;

                // k via F2I; f via parallel F2F.RZI (off the address chain)
                int k = (int)u;
                float fl = truncf(u);
                k = min(k, GRID_P - 1);
                fl = fminf(fl, (float)(GRID_P - 1));
                float f = u - fl;

                uint2 w = *(const uint2*)(T + (((size_t)(pr * NPTS + k)) << 4) + 2 * q);
                float r0, r1;
                if (q == 6) {
                    r0 = fmaf(f, __uint_as_float(w.y), __uint_as_float(w.x));  // u_next
                    r1 = 0.f;
                } else {
                    float2 f0 = __half22float2(u32_as_h2(w.x));
                    float2 f1 = __half22float2(u32_as_h2(w.y));
                    r0 = fmaf(f, f0.y, f0.x);
                    r1 = fmaf(f, f1.y, f1.x);
                }

                if (doStore) *(float2*)(pbase + tt * pstride) = make_float2(r0, r1);

                // q==6 r0 = u_next; broadcast within 8-lane group
                u = __shfl_sync(0xffffffffu, r0, psrc, 32);
            }
        }
        __syncthreads();

        // DMA this chunk's staging out (smem -> gmem, bypassing the register path)
        if (tid < 64) {
            fence_async_shared();
            bulk_s2g(bdst0 + (size_t)c * bstep, bsrc, bbytes);
            bulk_commit();
        }
    }

    // writes must be complete/visible before the grid exits
    if (tid < 64) bulk_wait0();
}

extern "C" void kernel_launch(void* const* d_in, const int* in_sizes, int n_in,
                              void* d_out, int out_size) {
    const int*   a  = (const int*)d_in[0];
    const int*   b  = (const int*)d_in[1];
    const float* Ea = (const float*)d_in[2];
    const float* Eb = (const float*)d_in[3];
    const float* W1 = (const float*)d_in[4];
    const float* b1 = (const float*)d_in[5];
    const float* W2 = (const float*)d_in[6];
    const float* b2 = (const float*)d_in[7];
    const float* Wd = (const float*)d_in[8];
    const float* bd = (const float*)d_in[9];
    const float* Wc = (const float*)d_in[10];
    const float* bc = (const float*)d_in[11];

    build_vals<<<(NPAIR * NPTS + 63) / 64, 256>>>(Ea, Eb, W1, b1, W2, b2, Wd, bd, Wc, bc);
    finalize_tab<<<(NPAIR * NPTS + 255) / 256, 256>>>();
    mlp_lookup<<<NB / 32, 256>>>(a, b, (float*)d_out);
}

// round 14
// speedup vs baseline: 1.1184x; 1.1184x over previous
#include <cuda_runtime.h>
#include <cuda_fp16.h>
#include <cstdint>

#define NB 65536
#define NL 64
#define GRID_P 256           // interpolation grid resolution
#define NPTS (GRID_P + 1)    // 257 points per pair
#define NPAIR 100
#define ROWS_CTA 16          // rows per lookup CTA (128 threads)
#define SDG_RS 168           // digit staging row stride (floats), mod 32 = 8, 16B-aligned rows
#define SCAR_RS 36           // carry staging row stride (floats)

typedef unsigned long long ull;

// ---- device scratch (no allocations allowed) ----
// fp32 scratch: 16 floats/entry: [0..11] logits, [12..15] pad
__device__ __align__(128) float g_scratch[(size_t)NPAIR * NPTS * 16];
// compact table: 16 uints (64B)/entry:
//   uint j (0..11) = half2(val_j, val_j(k+1)-val_j(k))
//   uint 12 = fp32 u_next val (p*GRID_P), uint 13 = fp32 u_next delta, 14..15 pad
__device__ __align__(128) unsigned int g_tab16[(size_t)NPAIR * NPTS * 16];

// ---- bit-reinterpret helpers ----
__device__ __forceinline__ unsigned int h2_as_u32(__half2 h) {
    return *reinterpret_cast<unsigned int*>(&h);
}
__device__ __forceinline__ __half2 u32_as_h2(unsigned int u) {
    return *reinterpret_cast<__half2*>(&u);
}

// ---- f32x2 helpers ----
__device__ __forceinline__ ull pack2(float x, float y) {
    ull r; asm("mov.b64 %0, {%1,%2};" : "=l"(r) : "f"(x), "f"(y)); return r;
}
__device__ __forceinline__ void unpack2(ull a, float &x, float &y) {
    asm("mov.b64 {%0,%1}, %2;" : "=f"(x), "=f"(y) : "l"(a));
}
__device__ __forceinline__ void ffma2(ull &c, ull a, ull b) {
    asm("fma.rn.f32x2 %0, %1, %2, %0;" : "+l"(c) : "l"(a), "l"(b));
}
__device__ __forceinline__ ull add2(ull a, ull b) {
    ull r; asm("add.rn.f32x2 %0, %1, %2;" : "=l"(r) : "l"(a), "l"(b)); return r;
}
__device__ __forceinline__ ull fma2v(ull a, ull b, ull c) {
    ull r; asm("fma.rn.f32x2 %0, %1, %2, %3;" : "=l"(r) : "l"(a), "l"(b), "l"(c)); return r;
}

// ---- bulk smem->gmem copy helpers ----
__device__ __forceinline__ void bulk_s2g(void* dst, const void* smem_src, unsigned bytes) {
    unsigned s = (unsigned)__cvta_generic_to_shared(smem_src);
    asm volatile("cp.async.bulk.global.shared::cta.bulk_group [%0], [%1], %2;"
        :: "l"(dst), "r"(s), "r"(bytes) : "memory");
}
__device__ __forceinline__ void bulk_commit() {
    asm volatile("cp.async.bulk.commit_group;" ::: "memory");
}
__device__ __forceinline__ void bulk_wait_read0() {
    asm volatile("cp.async.bulk.wait_group.read 0;" ::: "memory");
}
__device__ __forceinline__ void bulk_wait0() {
    asm volatile("cp.async.bulk.wait_group 0;" ::: "memory");
}
__device__ __forceinline__ void fence_async_shared() {
    asm volatile("fence.proxy.async.shared::cta;" ::: "memory");
}

// ---- build fp32 scratch (prep folded): one thread per (pair, gridpoint) ----
__global__ void __launch_bounds__(256) build_vals(
    const float* __restrict__ Ea, const float* __restrict__ Eb,
    const float* __restrict__ W1, const float* __restrict__ b1,
    const float* __restrict__ W2, const float* __restrict__ b2,
    const float* __restrict__ Wd, const float* __restrict__ bd,
    const float* __restrict__ Wc, const float* __restrict__ bc)
{
    __shared__ __align__(16) float sTa[660], sTb[660];
    __shared__ __align__(16) float sv[64];
    __shared__ __align__(16) float sW2p[2048];   // [j][i] transposed; (i,i+1) pairs contiguous
    __shared__ __align__(16) float sHd[384];     // [i][d]: 12 head weights per unit i
    __shared__ __align__(16) float sB2[32];
    __shared__ __align__(16) float sBdc[16];

    int tid = threadIdx.x;  // 256
    for (int n = tid; n < 640; n += 256) {
        int j = n & 63, d = n >> 6;
        float w16 = W1[j * 18 + 16];
        float sa = 0.f, sb = 0.f;
        #pragma unroll
        for (int k = 0; k < 8; k++) {
            sa += Ea[d * 8 + k] * W1[j * 18 + k];
            sb += Eb[d * 8 + k] * W1[j * 18 + 8 + k];
        }
        sTa[d * 66 + j] = b1[j] + w16 + sa;
        sTb[d * 66 + j] = sb;
    }
    if (tid < 64) sv[tid] = W1[tid * 18 + 17] - W1[tid * 18 + 16];
    for (int n = tid; n < 2048; n += 256) { int j = n >> 5, i = n & 31; sW2p[n] = W2[i * 64 + j]; }
    for (int n = tid; n < 384; n += 256) {
        int i = n / 12, d = n % 12;
        sHd[n] = (d < 10) ? Wd[d * 32 + i] : Wc[(d - 10) * 32 + i];
    }
    if (tid < 32) sB2[tid] = b2[tid];
    if (tid < 16) sBdc[tid] = (tid < 10) ? bd[tid] : (tid < 12 ? bc[tid - 10] : 0.f);
    __syncthreads();

    int e = blockIdx.x * 256 + tid;
    if (e >= NPAIR * NPTS) return;
    int pr = e / NPTS;
    int k = e - pr * NPTS;
    int a0 = pr / 10, b0 = pr - a0 * 10;
    float p = (float)k * (1.0f / (float)GRID_P);

    const float* ta = sTa + a0 * 66;
    const float* tb = sTb + b0 * 66;
    ull pp = pack2(p, p);

    ull acc[16];
    {
        const ulonglong2* bp = (const ulonglong2*)sB2;
        #pragma unroll
        for (int q = 0; q < 8; q++) { ulonglong2 v2 = bp[q]; acc[2 * q] = v2.x; acc[2 * q + 1] = v2.y; }
    }
    #pragma unroll
    for (int jc = 0; jc < 4; jc++) {
        ull hh[16];
        #pragma unroll
        for (int jp = 0; jp < 8; jp++) {
            int j = jc * 16 + jp * 2;
            ull s = fma2v(pp, *(const ull*)(sv + j),
                          add2(*(const ull*)(ta + j), *(const ull*)(tb + j)));
            float x, y; unpack2(s, x, y);
            x = fmaxf(x, 0.f); y = fmaxf(y, 0.f);
            hh[2 * jp] = pack2(x, x);
            hh[2 * jp + 1] = pack2(y, y);
        }
        #pragma unroll
        for (int jj = 0; jj < 16; jj++) {
            int j = jc * 16 + jj;
            ull h = hh[jj];
            const ulonglong2* wp = (const ulonglong2*)(sW2p + j * 32);
            #pragma unroll
            for (int q = 0; q < 8; q++) {
                ulonglong2 w = wp[q];
                ffma2(acc[2 * q], h, w.x);
                ffma2(acc[2 * q + 1], h, w.y);
            }
        }
    }

    ull hacc[6];
    {
        const ulonglong2* hb = (const ulonglong2*)sBdc;
        ulonglong2 h0 = hb[0], h1b = hb[1], h2b = hb[2];
        hacc[0] = h0.x; hacc[1] = h0.y; hacc[2] = h1b.x;
        hacc[3] = h1b.y; hacc[4] = h2b.x; hacc[5] = h2b.y;
    }
    #pragma unroll
    for (int q = 0; q < 16; q++) {
        float x, y; unpack2(acc[q], x, y);
        x = fmaxf(x, 0.f); y = fmaxf(y, 0.f);
        ull hx = pack2(x, x), hy = pack2(y, y);
        const ulonglong2* wp = (const ulonglong2*)(sHd + (2 * q) * 12);
        ulonglong2 w0 = wp[0], w1 = wp[1], w2 = wp[2];
        ffma2(hacc[0], hx, w0.x); ffma2(hacc[1], hx, w0.y);
        ffma2(hacc[2], hx, w1.x); ffma2(hacc[3], hx, w1.y);
        ffma2(hacc[4], hx, w2.x); ffma2(hacc[5], hx, w2.y);
        const ulonglong2* wq = (const ulonglong2*)(sHd + (2 * q + 1) * 12);
        ulonglong2 u0 = wq[0], u1 = wq[1], u2 = wq[2];
        ffma2(hacc[0], hy, u0.x); ffma2(hacc[1], hy, u0.y);
        ffma2(hacc[2], hy, u1.x); ffma2(hacc[3], hy, u1.y);
        ffma2(hacc[4], hy, u2.x); ffma2(hacc[5], hy, u2.y);
    }

    float* o = g_scratch + (size_t)e * 16;
    *(ull*)(o + 0)  = hacc[0];
    *(ull*)(o + 2)  = hacc[1];
    *(ull*)(o + 4)  = hacc[2];
    *(ull*)(o + 6)  = hacc[3];
    *(ull*)(o + 8)  = hacc[4];
    *(ull*)(o + 10) = hacc[5];
    o[12] = 0.f; o[13] = 0.f; o[14] = 0.f; o[15] = 0.f;
}

// ---- finalize compact table: one thread per entry (computes scaled u_next) ----
__global__ void __launch_bounds__(256) finalize_tab() {
    int e = blockIdx.x * 256 + threadIdx.x;
    if (e >= NPAIR * NPTS) return;
    int pr = e / NPTS;
    int k = e - pr * NPTS;
    int en = (k < GRID_P) ? (e + 1) : e;      // neighbor (delta=0 at the last point)

    const float4* c0 = (const float4*)(g_scratch + (size_t)e * 16);
    const float4* c1 = (const float4*)(g_scratch + (size_t)en * 16);
    float4 v0 = c0[0], v1 = c0[1], v2 = c0[2];
    float4 n0 = c1[0], n1 = c1[1], n2 = c1[2];

    // u_next = p_next * GRID_P (pre-scaled recursion state)
    float pv = (float)GRID_P / (1.f + __expf(v2.z - v2.w));
    float pn = (float)GRID_P / (1.f + __expf(n2.z - n2.w));

    unsigned int* o = g_tab16 + (size_t)e * 16;
    uint4 w;
    w.x = h2_as_u32(__floats2half2_rn(v0.x, n0.x - v0.x));
    w.y = h2_as_u32(__floats2half2_rn(v0.y, n0.y - v0.y));
    w.z = h2_as_u32(__floats2half2_rn(v0.z, n0.z - v0.z));
    w.w = h2_as_u32(__floats2half2_rn(v0.w, n0.w - v0.w));
    ((uint4*)o)[0] = w;
    w.x = h2_as_u32(__floats2half2_rn(v1.x, n1.x - v1.x));
    w.y = h2_as_u32(__floats2half2_rn(v1.y, n1.y - v1.y));
    w.z = h2_as_u32(__floats2half2_rn(v1.z, n1.z - v1.z));
    w.w = h2_as_u32(__floats2half2_rn(v1.w, n1.w - v1.w));
    ((uint4*)o)[1] = w;
    w.x = h2_as_u32(__floats2half2_rn(v2.x, n2.x - v2.x));
    w.y = h2_as_u32(__floats2half2_rn(v2.y, n2.y - v2.y));
    w.z = h2_as_u32(__floats2half2_rn(v2.z, n2.z - v2.z));
    w.w = h2_as_u32(__floats2half2_rn(v2.w, n2.w - v2.w));
    ((uint4*)o)[2] = w;
    w.x = __float_as_uint(pv);
    w.y = __float_as_uint(pn - pv);
    w.z = 0u; w.w = 0u;
    ((uint4*)o)[3] = w;
}

// ---- main: 8 lanes/row, 16 rows/CTA (128 thr) to leave L1 for table ----
__global__ void __launch_bounds__(128, 8) mlp_lookup(
    const int* __restrict__ aI, const int* __restrict__ bI, float* __restrict__ out)
{
    __shared__ __align__(16) unsigned char sdig[ROWS_CTA * 64];   // [row][t] pair index
    __shared__ __align__(16) float sdg[ROWS_CTA * SDG_RS];        // [row][tt*10+d]
    __shared__ __align__(16) float scar[ROWS_CTA * SCAR_RS];      // [row][tt*2+k]
    __shared__ int sflagA, sflagB;

    int tid = threadIdx.x;           // 128
    int lrow = tid >> 3;             // 0..15 (row within CTA)
    int q = tid & 7;                 // lane within 8-lane row group
    int lane = tid & 31;
    int rowbase = blockIdx.x * ROWS_CTA;

    // dtype sniff: int64 viewed as int32 has high words (odd indices) all zero
    if (tid < 32) {
        int v = aI[2 * tid + 1];
        unsigned m = __ballot_sync(0xffffffffu, v == 0);
        if (tid == 0) sflagA = (m == 0xffffffffu);
    } else if (tid < 64) {
        int l = tid - 32;
        int v = bI[2 * l + 1];
        unsigned m = __ballot_sync(0xffffffffu, v == 0);
        if (l == 0) sflagB = (m == 0xffffffffu);
    }
    __syncthreads();
    bool f64a = sflagA != 0, f64b = sflagB != 0;

    // load + transpose this CTA's digits into smem (16 rows x 64 t)
    #pragma unroll
    for (int kk = 0; kk < 8; kk++) {
        int i = tid + kk * 128;      // 0..1023
        int r = i >> 6, t = i & 63;
        size_t idx = (size_t)(rowbase + r) * NL + t;
        int av = f64a ? aI[2 * idx] : aI[idx];
        int bv = f64b ? bI[2 * idx] : bI[idx];
        sdig[r * 64 + t] = (unsigned char)(av * 10 + bv);
    }
    __syncthreads();

    // per-thread store routing (loop-invariant): q 0-4 -> digits, q 5 -> carry
    float* digrow = sdg + lrow * SDG_RS;
    float* carrow = scar + lrow * SCAR_RS;
    bool doStore = (q < 6);
    float* pbase = (q < 5) ? (digrow + 2 * q) : carrow;
    int pstride = (q < 5) ? 10 : 2;
    int psrc = (lane & 24) | 6;      // lane holding u_next (q==6) in this 8-lane group

    // bulk-copy routing (tid < 32 issues one copy per chunk)
    float* bdst0 = 0; const float* bsrc = 0; unsigned bbytes = 0; int bstep = 0;
    float* outc_base = out + (size_t)NB * NL * 10;
    if (tid < ROWS_CTA) {
        bdst0 = out + (size_t)(rowbase + tid) * (NL * 10);
        bsrc = sdg + tid * SDG_RS;
        bbytes = 640; bstep = 160;
    } else if (tid < 2 * ROWS_CTA) {
        int r = tid - ROWS_CTA;
        bdst0 = outc_base + (size_t)(rowbase + r) * (NL * 2);
        bsrc = scar + r * SCAR_RS;
        bbytes = 128; bstep = 32;
    }

    const unsigned int* T = g_tab16;
    float u = 0.f;   // scaled recursion state u = p * GRID_P; t=0 carry = [1,0] <=> u = 0

    #pragma unroll 1
    for (int c = 0; c < 4; c++) {
        if (c > 0) {
            if (tid < 2 * ROWS_CTA) bulk_wait_read0();   // staging free for reuse
            __syncthreads();
        }

        // 16 pair-bytes for this chunk in one LDS.128
        uint4 dw = *(const uint4*)(sdig + lrow * 64 + c * 16);

        #pragma unroll 1
        for (int tt4 = 0; tt4 < 4; tt4++) {
            unsigned w4 = (tt4 == 0) ? dw.x : (tt4 == 1) ? dw.y : (tt4 == 2) ? dw.z : dw.w;
            #pragma unroll
            for (int s = 0; s < 4; s++) {
                int tt = tt4 * 4 + s;
                int pr = (w4 >> (8 * s)) & 255;

                // k via F2I; f via parallel F2F.RZI (off the address chain)
                int k = (int)u;
                float fl = truncf(u);
                k = min(k, GRID_P - 1);
                fl = fminf(fl, (float)(GRID_P - 1));
                float f = u - fl;

                uint2 w = *(const uint2*)(T + (((size_t)(pr * NPTS + k)) << 4) + 2 * q);
                float r0, r1;
                if (q == 6) {
                    r0 = fmaf(f, __uint_as_float(w.y), __uint_as_float(w.x));  // u_next
                    r1 = 0.f;
                } else {
                    float2 f0 = __half22float2(u32_as_h2(w.x));
                    float2 f1 = __half22float2(u32_as_h2(w.y));
                    r0 = fmaf(f, f0.y, f0.x);
                    r1 = fmaf(f, f1.y, f1.x);
                }

                if (doStore) *(float2*)(pbase + tt * pstride) = make_float2(r0, r1);

                // q==6 r0 = u_next; broadcast within 8-lane group
                u = __shfl_sync(0xffffffffu, r0, psrc, 32);
            }
        }
        __syncthreads();

        // DMA this chunk's staging out (smem -> gmem, bypassing the register path)
        if (tid < 2 * ROWS_CTA) {
            fence_async_shared();
            bulk_s2g(bdst0 + (size_t)c * bstep, bsrc, bbytes);
            bulk_commit();
        }
    }

    // writes must be complete/visible before the grid exits
    if (tid < 2 * ROWS_CTA) bulk_wait0();
}

extern "C" void kernel_launch(void* const* d_in, const int* in_sizes, int n_in,
                              void* d_out, int out_size) {
    const int*   a  = (const int*)d_in[0];
    const int*   b  = (const int*)d_in[1];
    const float* Ea = (const float*)d_in[2];
    const float* Eb = (const float*)d_in[3];
    const float* W1 = (const float*)d_in[4];
    const float* b1 = (const float*)d_in[5];
    const float* W2 = (const float*)d_in[6];
    const float* b2 = (const float*)d_in[7];
    const float* Wd = (const float*)d_in[8];
    const float* bd = (const float*)d_in[9];
    const float* Wc = (const float*)d_in[10];
    const float* bc = (const float*)d_in[11];

    build_vals<<<(NPAIR * NPTS + 255) / 256, 256>>>(Ea, Eb, W1, b1, W2, b2, Wd, bd, Wc, bc);
    finalize_tab<<<(NPAIR * NPTS + 255) / 256, 256>>>();
    mlp_lookup<<<NB / ROWS_CTA, 128>>>(a, b, (float*)d_out);
}

// round 15
// speedup vs baseline: 1.2681x; 1.1338x over previous
#include <cuda_runtime.h>
#include <cuda_fp16.h>
#include <cstdint>

#define NB 65536
#define NL 64
#define GRID_P 256           // interpolation grid resolution
#define NPTS (GRID_P + 1)    // 257 points per pair
#define NPAIR 100
#define ROWS_CTA 64          // rows per lookup CTA (256 threads, 4 lanes/row)
#define SDG_RS 84            // digit staging row stride (floats): 8 steps x 10 + 4 pad, 16B mult
#define SCAR_RS 20           // carry staging row stride (floats): 8 steps x 2 + 4 pad, 16B mult

typedef unsigned long long ull;

// ---- device scratch (no allocations allowed) ----
// fp32 scratch: 16 floats/entry: [0..11] logits, [12..15] pad
__device__ __align__(128) float g_scratch[(size_t)NPAIR * NPTS * 16];
// compact table: 16 uints (64B)/entry:
//   uint j (0..11) = half2(val_j, val_j(k+1)-val_j(k))
//   uint 12 = fp32 u_next val (p*GRID_P), uint 13 = fp32 u_next delta, 14..15 pad
__device__ __align__(128) unsigned int g_tab16[(size_t)NPAIR * NPTS * 16];

// ---- bit-reinterpret helpers ----
__device__ __forceinline__ unsigned int h2_as_u32(__half2 h) {
    return *reinterpret_cast<unsigned int*>(&h);
}
__device__ __forceinline__ __half2 u32_as_h2(unsigned int u) {
    return *reinterpret_cast<__half2*>(&u);
}

// ---- f32x2 helpers ----
__device__ __forceinline__ ull pack2(float x, float y) {
    ull r; asm("mov.b64 %0, {%1,%2};" : "=l"(r) : "f"(x), "f"(y)); return r;
}
__device__ __forceinline__ void unpack2(ull a, float &x, float &y) {
    asm("mov.b64 {%0,%1}, %2;" : "=f"(x), "=f"(y) : "l"(a));
}
__device__ __forceinline__ void ffma2(ull &c, ull a, ull b) {
    asm("fma.rn.f32x2 %0, %1, %2, %0;" : "+l"(c) : "l"(a), "l"(b));
}
__device__ __forceinline__ ull add2(ull a, ull b) {
    ull r; asm("add.rn.f32x2 %0, %1, %2;" : "=l"(r) : "l"(a), "l"(b)); return r;
}
__device__ __forceinline__ ull fma2v(ull a, ull b, ull c) {
    ull r; asm("fma.rn.f32x2 %0, %1, %2, %3;" : "=l"(r) : "l"(a), "l"(b), "l"(c)); return r;
}

// ---- bulk smem->gmem copy helpers ----
__device__ __forceinline__ void bulk_s2g(void* dst, const void* smem_src, unsigned bytes) {
    unsigned s = (unsigned)__cvta_generic_to_shared(smem_src);
    asm volatile("cp.async.bulk.global.shared::cta.bulk_group [%0], [%1], %2;"
        :: "l"(dst), "r"(s), "r"(bytes) : "memory");
}
__device__ __forceinline__ void bulk_commit() {
    asm volatile("cp.async.bulk.commit_group;" ::: "memory");
}
__device__ __forceinline__ void bulk_wait_read0() {
    asm volatile("cp.async.bulk.wait_group.read 0;" ::: "memory");
}
__device__ __forceinline__ void bulk_wait0() {
    asm volatile("cp.async.bulk.wait_group 0;" ::: "memory");
}
__device__ __forceinline__ void fence_async_shared() {
    asm volatile("fence.proxy.async.shared::cta;" ::: "memory");
}

// ---- build fp32 scratch (prep folded): one thread per (pair, gridpoint) ----
__global__ void __launch_bounds__(256) build_vals(
    const float* __restrict__ Ea, const float* __restrict__ Eb,
    const float* __restrict__ W1, const float* __restrict__ b1,
    const float* __restrict__ W2, const float* __restrict__ b2,
    const float* __restrict__ Wd, const float* __restrict__ bd,
    const float* __restrict__ Wc, const float* __restrict__ bc)
{
    __shared__ __align__(16) float sTa[660], sTb[660];
    __shared__ __align__(16) float sv[64];
    __shared__ __align__(16) float sW2p[2048];   // [j][i] transposed; (i,i+1) pairs contiguous
    __shared__ __align__(16) float sHd[384];     // [i][d]: 12 head weights per unit i
    __shared__ __align__(16) float sB2[32];
    __shared__ __align__(16) float sBdc[16];

    int tid = threadIdx.x;  // 256
    for (int n = tid; n < 640; n += 256) {
        int j = n & 63, d = n >> 6;
        float w16 = W1[j * 18 + 16];
        float sa = 0.f, sb = 0.f;
        #pragma unroll
        for (int k = 0; k < 8; k++) {
            sa += Ea[d * 8 + k] * W1[j * 18 + k];
            sb += Eb[d * 8 + k] * W1[j * 18 + 8 + k];
        }
        sTa[d * 66 + j] = b1[j] + w16 + sa;
        sTb[d * 66 + j] = sb;
    }
    if (tid < 64) sv[tid] = W1[tid * 18 + 17] - W1[tid * 18 + 16];
    for (int n = tid; n < 2048; n += 256) { int j = n >> 5, i = n & 31; sW2p[n] = W2[i * 64 + j]; }
    for (int n = tid; n < 384; n += 256) {
        int i = n / 12, d = n % 12;
        sHd[n] = (d < 10) ? Wd[d * 32 + i] : Wc[(d - 10) * 32 + i];
    }
    if (tid < 32) sB2[tid] = b2[tid];
    if (tid < 16) sBdc[tid] = (tid < 10) ? bd[tid] : (tid < 12 ? bc[tid - 10] : 0.f);
    __syncthreads();

    int e = blockIdx.x * 256 + tid;
    if (e >= NPAIR * NPTS) return;
    int pr = e / NPTS;
    int k = e - pr * NPTS;
    int a0 = pr / 10, b0 = pr - a0 * 10;
    float p = (float)k * (1.0f / (float)GRID_P);

    const float* ta = sTa + a0 * 66;
    const float* tb = sTb + b0 * 66;
    ull pp = pack2(p, p);

    ull acc[16];
    {
        const ulonglong2* bp = (const ulonglong2*)sB2;
        #pragma unroll
        for (int q = 0; q < 8; q++) { ulonglong2 v2 = bp[q]; acc[2 * q] = v2.x; acc[2 * q + 1] = v2.y; }
    }
    #pragma unroll
    for (int jc = 0; jc < 4; jc++) {
        ull hh[16];
        #pragma unroll
        for (int jp = 0; jp < 8; jp++) {
            int j = jc * 16 + jp * 2;
            ull s = fma2v(pp, *(const ull*)(sv + j),
                          add2(*(const ull*)(ta + j), *(const ull*)(tb + j)));
            float x, y; unpack2(s, x, y);
            x = fmaxf(x, 0.f); y = fmaxf(y, 0.f);
            hh[2 * jp] = pack2(x, x);
            hh[2 * jp + 1] = pack2(y, y);
        }
        #pragma unroll
        for (int jj = 0; jj < 16; jj++) {
            int j = jc * 16 + jj;
            ull h = hh[jj];
            const ulonglong2* wp = (const ulonglong2*)(sW2p + j * 32);
            #pragma unroll
            for (int q = 0; q < 8; q++) {
                ulonglong2 w = wp[q];
                ffma2(acc[2 * q], h, w.x);
                ffma2(acc[2 * q + 1], h, w.y);
            }
        }
    }

    ull hacc[6];
    {
        const ulonglong2* hb = (const ulonglong2*)sBdc;
        ulonglong2 h0 = hb[0], h1b = hb[1], h2b = hb[2];
        hacc[0] = h0.x; hacc[1] = h0.y; hacc[2] = h1b.x;
        hacc[3] = h1b.y; hacc[4] = h2b.x; hacc[5] = h2b.y;
    }
    #pragma unroll
    for (int q = 0; q < 16; q++) {
        float x, y; unpack2(acc[q], x, y);
        x = fmaxf(x, 0.f); y = fmaxf(y, 0.f);
        ull hx = pack2(x, x), hy = pack2(y, y);
        const ulonglong2* wp = (const ulonglong2*)(sHd + (2 * q) * 12);
        ulonglong2 w0 = wp[0], w1 = wp[1], w2 = wp[2];
        ffma2(hacc[0], hx, w0.x); ffma2(hacc[1], hx, w0.y);
        ffma2(hacc[2], hx, w1.x); ffma2(hacc[3], hx, w1.y);
        ffma2(hacc[4], hx, w2.x); ffma2(hacc[5], hx, w2.y);
        const ulonglong2* wq = (const ulonglong2*)(sHd + (2 * q + 1) * 12);
        ulonglong2 u0 = wq[0], u1 = wq[1], u2 = wq[2];
        ffma2(hacc[0], hy, u0.x); ffma2(hacc[1], hy, u0.y);
        ffma2(hacc[2], hy, u1.x); ffma2(hacc[3], hy, u1.y);
        ffma2(hacc[4], hy, u2.x); ffma2(hacc[5], hy, u2.y);
    }

    float* o = g_scratch + (size_t)e * 16;
    *(ull*)(o + 0)  = hacc[0];
    *(ull*)(o + 2)  = hacc[1];
    *(ull*)(o + 4)  = hacc[2];
    *(ull*)(o + 6)  = hacc[3];
    *(ull*)(o + 8)  = hacc[4];
    *(ull*)(o + 10) = hacc[5];
    o[12] = 0.f; o[13] = 0.f; o[14] = 0.f; o[15] = 0.f;
}

// ---- finalize compact table: one thread per entry (computes scaled u_next) ----
__global__ void __launch_bounds__(256) finalize_tab() {
    int e = blockIdx.x * 256 + threadIdx.x;
    if (e >= NPAIR * NPTS) return;
    int pr = e / NPTS;
    int k = e - pr * NPTS;
    int en = (k < GRID_P) ? (e + 1) : e;      // neighbor (delta=0 at the last point)

    const float4* c0 = (const float4*)(g_scratch + (size_t)e * 16);
    const float4* c1 = (const float4*)(g_scratch + (size_t)en * 16);
    float4 v0 = c0[0], v1 = c0[1], v2 = c0[2];
    float4 n0 = c1[0], n1 = c1[1], n2 = c1[2];

    // u_next = p_next * GRID_P (pre-scaled recursion state)
    float pv = (float)GRID_P / (1.f + __expf(v2.z - v2.w));
    float pn = (float)GRID_P / (1.f + __expf(n2.z - n2.w));

    unsigned int* o = g_tab16 + (size_t)e * 16;
    uint4 w;
    w.x = h2_as_u32(__floats2half2_rn(v0.x, n0.x - v0.x));
    w.y = h2_as_u32(__floats2half2_rn(v0.y, n0.y - v0.y));
    w.z = h2_as_u32(__floats2half2_rn(v0.z, n0.z - v0.z));
    w.w = h2_as_u32(__floats2half2_rn(v0.w, n0.w - v0.w));
    ((uint4*)o)[0] = w;
    w.x = h2_as_u32(__floats2half2_rn(v1.x, n1.x - v1.x));
    w.y = h2_as_u32(__floats2half2_rn(v1.y, n1.y - v1.y));
    w.z = h2_as_u32(__floats2half2_rn(v1.z, n1.z - v1.z));
    w.w = h2_as_u32(__floats2half2_rn(v1.w, n1.w - v1.w));
    ((uint4*)o)[1] = w;
    w.x = h2_as_u32(__floats2half2_rn(v2.x, n2.x - v2.x));
    w.y = h2_as_u32(__floats2half2_rn(v2.y, n2.y - v2.y));
    w.z = h2_as_u32(__floats2half2_rn(v2.z, n2.z - v2.z));
    w.w = h2_as_u32(__floats2half2_rn(v2.w, n2.w - v2.w));
    ((uint4*)o)[2] = w;
    w.x = __float_as_uint(pv);
    w.y = __float_as_uint(pn - pv);
    w.z = 0u; w.w = 0u;
    ((uint4*)o)[3] = w;
}

// ---- main: 4 lanes/row, 64 rows/CTA, 8-step chunks, bulk-copy output ----
__global__ void __launch_bounds__(256) mlp_lookup(
    const int* __restrict__ aI, const int* __restrict__ bI, float* __restrict__ out)
{
    __shared__ __align__(16) unsigned char sdig[ROWS_CTA * 64];   // [row][t] pair index
    __shared__ __align__(16) float sdg[ROWS_CTA * SDG_RS];        // [row][s*10+d]
    __shared__ __align__(16) float scar[ROWS_CTA * SCAR_RS];      // [row][s*2+k]
    __shared__ int sflagA, sflagB;

    int tid = threadIdx.x;           // 256
    int lrow = tid >> 2;             // 0..63 (row within CTA)
    int q = tid & 3;                 // lane within 4-lane row group
    int lane = tid & 31;
    int rowbase = blockIdx.x * ROWS_CTA;

    // dtype sniff: int64 viewed as int32 has high words (odd indices) all zero
    if (tid < 32) {
        int v = aI[2 * tid + 1];
        unsigned m = __ballot_sync(0xffffffffu, v == 0);
        if (tid == 0) sflagA = (m == 0xffffffffu);
    } else if (tid < 64) {
        int l = tid - 32;
        int v = bI[2 * l + 1];
        unsigned m = __ballot_sync(0xffffffffu, v == 0);
        if (l == 0) sflagB = (m == 0xffffffffu);
    }
    __syncthreads();
    bool f64a = sflagA != 0, f64b = sflagB != 0;

    // load + transpose this CTA's digits into smem (64 rows x 64 t)
    #pragma unroll
    for (int kk = 0; kk < 16; kk++) {
        int i = tid + kk * 256;      // 0..4095
        int r = i >> 6, t = i & 63;
        size_t idx = (size_t)(rowbase + r) * NL + t;
        int av = f64a ? aI[2 * idx] : aI[idx];
        int bv = f64b ? bI[2 * idx] : bI[idx];
        sdig[r * 64 + t] = (unsigned char)(av * 10 + bv);
    }
    __syncthreads();

    // per-thread store routing (loop-invariant): q0/q1/q2 store, q3 is the u lane
    float* digrow = sdg + lrow * SDG_RS;
    float* carrow = scar + lrow * SCAR_RS;
    float *p1, *p2; int st1, st2;
    if (q == 0)      { p1 = digrow;     st1 = 10; p2 = digrow + 2; st2 = 10; }
    else if (q == 1) { p1 = digrow + 4; st1 = 10; p2 = digrow + 6; st2 = 10; }
    else if (q == 2) { p1 = digrow + 8; st1 = 10; p2 = carrow;     st2 = 2;  }
    else             { p1 = digrow;     st1 = 0;  p2 = digrow;     st2 = 0;  }
    bool doStore = (q < 3);
    int psrc = lane | 3;             // lane holding u_next (q==3) in this 4-lane group

    // bulk-copy routing (tid < 128 issues one copy per chunk)
    float* bdst0 = 0; const float* bsrc = 0; unsigned bbytes = 0; int bstep = 0;
    float* outc_base = out + (size_t)NB * NL * 10;
    if (tid < ROWS_CTA) {
        bdst0 = out + (size_t)(rowbase + tid) * (NL * 10);
        bsrc = sdg + tid * SDG_RS;
        bbytes = 320; bstep = 80;
    } else if (tid < 2 * ROWS_CTA) {
        int r = tid - ROWS_CTA;
        bdst0 = outc_base + (size_t)(rowbase + r) * (NL * 2);
        bsrc = scar + r * SCAR_RS;
        bbytes = 64; bstep = 16;
    }

    const unsigned int* T = g_tab16;
    float u = 0.f;   // scaled recursion state u = p * GRID_P; t=0 carry = [1,0] <=> u = 0

    #pragma unroll 1
    for (int c = 0; c < 8; c++) {
        if (c > 0) {
            if (tid < 2 * ROWS_CTA) bulk_wait_read0();   // staging free for reuse
            __syncthreads();
        }

        // 8 pair-bytes for this chunk in one LDS.64
        ull w8 = *(const ull*)(sdig + lrow * 64 + c * 8);

        #pragma unroll
        for (int s = 0; s < 8; s++) {
            int pr = (int)((w8 >> (8 * s)) & 255u);

            // k via F2I; f via parallel F2F.RZI (off the address chain)
            int k = (int)u;
            float fl = truncf(u);
            k = min(k, GRID_P - 1);
            fl = fminf(fl, (float)(GRID_P - 1));
            float f = u - fl;

            uint4 w = *(const uint4*)(T + (((size_t)(pr * NPTS + k)) << 4) + 4 * q);
            float r0, r1, r2, r3;
            if (q == 3) {
                r0 = fmaf(f, __uint_as_float(w.y), __uint_as_float(w.x));  // u_next
                r1 = 0.f; r2 = 0.f; r3 = 0.f;
            } else {
                float2 a0 = __half22float2(u32_as_h2(w.x));
                float2 a1 = __half22float2(u32_as_h2(w.y));
                float2 a2 = __half22float2(u32_as_h2(w.z));
                float2 a3 = __half22float2(u32_as_h2(w.w));
                r0 = fmaf(f, a0.y, a0.x);
                r1 = fmaf(f, a1.y, a1.x);
                r2 = fmaf(f, a2.y, a2.x);
                r3 = fmaf(f, a3.y, a3.x);
            }

            if (doStore) {
                *(float2*)(p1 + s * st1) = make_float2(r0, r1);
                *(float2*)(p2 + s * st2) = make_float2(r2, r3);
            }

            // q==3 r0 = u_next; broadcast within 4-lane group
            u = __shfl_sync(0xffffffffu, r0, psrc, 32);
        }
        __syncthreads();

        // DMA this chunk's staging out (smem -> gmem, bypassing the register path)
        if (tid < 2 * ROWS_CTA) {
            fence_async_shared();
            bulk_s2g(bdst0 + (size_t)c * bstep, bsrc, bbytes);
            bulk_commit();
        }
    }

    // writes must be complete/visible before the grid exits
    if (tid < 2 * ROWS_CTA) bulk_wait0();
}

extern "C" void kernel_launch(void* const* d_in, const int* in_sizes, int n_in,
                              void* d_out, int out_size) {
    const int*   a  = (const int*)d_in[0];
    const int*   b  = (const int*)d_in[1];
    const float* Ea = (const float*)d_in[2];
    const float* Eb = (const float*)d_in[3];
    const float* W1 = (const float*)d_in[4];
    const float* b1 = (const float*)d_in[5];
    const float* W2 = (const float*)d_in[6];
    const float* b2 = (const float*)d_in[7];
    const float* Wd = (const float*)d_in[8];
    const float* bd = (const float*)d_in[9];
    const float* Wc = (const float*)d_in[10];
    const float* bc = (const float*)d_in[11];

    build_vals<<<(NPAIR * NPTS + 255) / 256, 256>>>(Ea, Eb, W1, b1, W2, b2, Wd, bd, Wc, bc);
    finalize_tab<<<(NPAIR * NPTS + 255) / 256, 256>>>();
    mlp_lookup<<<NB / ROWS_CTA, 256>>>(a, b, (float*)d_out);
}

// round 16
// speedup vs baseline: 1.3392x; 1.0561x over previous
#include <cuda_runtime.h>
#include <cuda_fp16.h>
#include <cstdint>

#define NB 65536
#define NL 64
#define GRID_P 128           // interpolation grid resolution
#define NPTS (GRID_P + 1)    // 129 points per pair
#define NPAIR 100
#define ROWS_CTA 64          // rows per lookup CTA (256 threads, 4 lanes/row)
#define SDG_RS 84            // digit staging row stride (floats): 8 steps x 10 + 4 pad, 16B mult
#define SCAR_RS 20           // carry staging row stride (floats): 8 steps x 2 + 4 pad, 16B mult

typedef unsigned long long ull;

// ---- device scratch (no allocations allowed) ----
// fp32 scratch: 16 floats/entry: [0..11] logits, [12..15] pad
__device__ __align__(128) float g_scratch[(size_t)NPAIR * NPTS * 16];
// compact table: 16 uints (64B)/entry:
//   uint j (0..11) = half2(val_j, val_j(k+1)-val_j(k))
//   uint 12 = fp32 u_next val (p*GRID_P), uint 13 = fp32 u_next delta, 14..15 pad
__device__ __align__(128) unsigned int g_tab16[(size_t)NPAIR * NPTS * 16];

// ---- bit-reinterpret helpers ----
__device__ __forceinline__ unsigned int h2_as_u32(__half2 h) {
    return *reinterpret_cast<unsigned int*>(&h);
}
__device__ __forceinline__ __half2 u32_as_h2(unsigned int u) {
    return *reinterpret_cast<__half2*>(&u);
}

// ---- f32x2 helpers ----
__device__ __forceinline__ ull pack2(float x, float y) {
    ull r; asm("mov.b64 %0, {%1,%2};" : "=l"(r) : "f"(x), "f"(y)); return r;
}
__device__ __forceinline__ void unpack2(ull a, float &x, float &y) {
    asm("mov.b64 {%0,%1}, %2;" : "=f"(x), "=f"(y) : "l"(a));
}
__device__ __forceinline__ void ffma2(ull &c, ull a, ull b) {
    asm("fma.rn.f32x2 %0, %1, %2, %0;" : "+l"(c) : "l"(a), "l"(b));
}
__device__ __forceinline__ ull add2(ull a, ull b) {
    ull r; asm("add.rn.f32x2 %0, %1, %2;" : "=l"(r) : "l"(a), "l"(b)); return r;
}
__device__ __forceinline__ ull fma2v(ull a, ull b, ull c) {
    ull r; asm("fma.rn.f32x2 %0, %1, %2, %3;" : "=l"(r) : "l"(a), "l"(b), "l"(c)); return r;
}

// ---- bulk smem->gmem copy helpers ----
__device__ __forceinline__ void bulk_s2g(void* dst, const void* smem_src, unsigned bytes) {
    unsigned s = (unsigned)__cvta_generic_to_shared(smem_src);
    asm volatile("cp.async.bulk.global.shared::cta.bulk_group [%0], [%1], %2;"
        :: "l"(dst), "r"(s), "r"(bytes) : "memory");
}
__device__ __forceinline__ void bulk_commit() {
    asm volatile("cp.async.bulk.commit_group;" ::: "memory");
}
__device__ __forceinline__ void bulk_wait_read0() {
    asm volatile("cp.async.bulk.wait_group.read 0;" ::: "memory");
}
__device__ __forceinline__ void bulk_wait0() {
    asm volatile("cp.async.bulk.wait_group 0;" ::: "memory");
}
__device__ __forceinline__ void fence_async_shared() {
    asm volatile("fence.proxy.async.shared::cta;" ::: "memory");
}

// ---- build fp32 scratch (prep folded): one thread per (pair, gridpoint) ----
__global__ void __launch_bounds__(256) build_vals(
    const float* __restrict__ Ea, const float* __restrict__ Eb,
    const float* __restrict__ W1, const float* __restrict__ b1,
    const float* __restrict__ W2, const float* __restrict__ b2,
    const float* __restrict__ Wd, const float* __restrict__ bd,
    const float* __restrict__ Wc, const float* __restrict__ bc)
{
    __shared__ __align__(16) float sTa[660], sTb[660];
    __shared__ __align__(16) float sv[64];
    __shared__ __align__(16) float sW2p[2048];   // [j][i] transposed; (i,i+1) pairs contiguous
    __shared__ __align__(16) float sHd[384];     // [i][d]: 12 head weights per unit i
    __shared__ __align__(16) float sB2[32];
    __shared__ __align__(16) float sBdc[16];

    int tid = threadIdx.x;  // 256
    for (int n = tid; n < 640; n += 256) {
        int j = n & 63, d = n >> 6;
        float w16 = W1[j * 18 + 16];
        float sa = 0.f, sb = 0.f;
        #pragma unroll
        for (int k = 0; k < 8; k++) {
            sa += Ea[d * 8 + k] * W1[j * 18 + k];
            sb += Eb[d * 8 + k] * W1[j * 18 + 8 + k];
        }
        sTa[d * 66 + j] = b1[j] + w16 + sa;
        sTb[d * 66 + j] = sb;
    }
    if (tid < 64) sv[tid] = W1[tid * 18 + 17] - W1[tid * 18 + 16];
    for (int n = tid; n < 2048; n += 256) { int j = n >> 5, i = n & 31; sW2p[n] = W2[i * 64 + j]; }
    for (int n = tid; n < 384; n += 256) {
        int i = n / 12, d = n % 12;
        sHd[n] = (d < 10) ? Wd[d * 32 + i] : Wc[(d - 10) * 32 + i];
    }
    if (tid < 32) sB2[tid] = b2[tid];
    if (tid < 16) sBdc[tid] = (tid < 10) ? bd[tid] : (tid < 12 ? bc[tid - 10] : 0.f);
    __syncthreads();

    int e = blockIdx.x * 256 + tid;
    if (e >= NPAIR * NPTS) return;
    int pr = e / NPTS;
    int k = e - pr * NPTS;
    int a0 = pr / 10, b0 = pr - a0 * 10;
    float p = (float)k * (1.0f / (float)GRID_P);

    const float* ta = sTa + a0 * 66;
    const float* tb = sTb + b0 * 66;
    ull pp = pack2(p, p);

    ull acc[16];
    {
        const ulonglong2* bp = (const ulonglong2*)sB2;
        #pragma unroll
        for (int q = 0; q < 8; q++) { ulonglong2 v2 = bp[q]; acc[2 * q] = v2.x; acc[2 * q + 1] = v2.y; }
    }
    #pragma unroll
    for (int jc = 0; jc < 4; jc++) {
        ull hh[16];
        #pragma unroll
        for (int jp = 0; jp < 8; jp++) {
            int j = jc * 16 + jp * 2;
            ull s = fma2v(pp, *(const ull*)(sv + j),
                          add2(*(const ull*)(ta + j), *(const ull*)(tb + j)));
            float x, y; unpack2(s, x, y);
            x = fmaxf(x, 0.f); y = fmaxf(y, 0.f);
            hh[2 * jp] = pack2(x, x);
            hh[2 * jp + 1] = pack2(y, y);
        }
        #pragma unroll
        for (int jj = 0; jj < 16; jj++) {
            int j = jc * 16 + jj;
            ull h = hh[jj];
            const ulonglong2* wp = (const ulonglong2*)(sW2p + j * 32);
            #pragma unroll
            for (int q = 0; q < 8; q++) {
                ulonglong2 w = wp[q];
                ffma2(acc[2 * q], h, w.x);
                ffma2(acc[2 * q + 1], h, w.y);
            }
        }
    }

    ull hacc[6];
    {
        const ulonglong2* hb = (const ulonglong2*)sBdc;
        ulonglong2 h0 = hb[0], h1b = hb[1], h2b = hb[2];
        hacc[0] = h0.x; hacc[1] = h0.y; hacc[2] = h1b.x;
        hacc[3] = h1b.y; hacc[4] = h2b.x; hacc[5] = h2b.y;
    }
    #pragma unroll
    for (int q = 0; q < 16; q++) {
        float x, y; unpack2(acc[q], x, y);
        x = fmaxf(x, 0.f); y = fmaxf(y, 0.f);
        ull hx = pack2(x, x), hy = pack2(y, y);
        const ulonglong2* wp = (const ulonglong2*)(sHd + (2 * q) * 12);
        ulonglong2 w0 = wp[0], w1 = wp[1], w2 = wp[2];
        ffma2(hacc[0], hx, w0.x); ffma2(hacc[1], hx, w0.y);
        ffma2(hacc[2], hx, w1.x); ffma2(hacc[3], hx, w1.y);
        ffma2(hacc[4], hx, w2.x); ffma2(hacc[5], hx, w2.y);
        const ulonglong2* wq = (const ulonglong2*)(sHd + (2 * q + 1) * 12);
        ulonglong2 u0 = wq[0], u1 = wq[1], u2 = wq[2];
        ffma2(hacc[0], hy, u0.x); ffma2(hacc[1], hy, u0.y);
        ffma2(hacc[2], hy, u1.x); ffma2(hacc[3], hy, u1.y);
        ffma2(hacc[4], hy, u2.x); ffma2(hacc[5], hy, u2.y);
    }

    float* o = g_scratch + (size_t)e * 16;
    *(ull*)(o + 0)  = hacc[0];
    *(ull*)(o + 2)  = hacc[1];
    *(ull*)(o + 4)  = hacc[2];
    *(ull*)(o + 6)  = hacc[3];
    *(ull*)(o + 8)  = hacc[4];
    *(ull*)(o + 10) = hacc[5];
    o[12] = 0.f; o[13] = 0.f; o[14] = 0.f; o[15] = 0.f;
}

// ---- finalize compact table: one thread per entry (computes scaled u_next) ----
__global__ void __launch_bounds__(256) finalize_tab() {
    int e = blockIdx.x * 256 + threadIdx.x;
    if (e >= NPAIR * NPTS) return;
    int pr = e / NPTS;
    int k = e - pr * NPTS;
    int en = (k < GRID_P) ? (e + 1) : e;      // neighbor (delta=0 at the last point)

    const float4* c0 = (const float4*)(g_scratch + (size_t)e * 16);
    const float4* c1 = (const float4*)(g_scratch + (size_t)en * 16);
    float4 v0 = c0[0], v1 = c0[1], v2 = c0[2];
    float4 n0 = c1[0], n1 = c1[1], n2 = c1[2];

    // u_next = p_next * GRID_P (pre-scaled recursion state)
    float pv = (float)GRID_P / (1.f + __expf(v2.z - v2.w));
    float pn = (float)GRID_P / (1.f + __expf(n2.z - n2.w));

    unsigned int* o = g_tab16 + (size_t)e * 16;
    uint4 w;
    w.x = h2_as_u32(__floats2half2_rn(v0.x, n0.x - v0.x));
    w.y = h2_as_u32(__floats2half2_rn(v0.y, n0.y - v0.y));
    w.z = h2_as_u32(__floats2half2_rn(v0.z, n0.z - v0.z));
    w.w = h2_as_u32(__floats2half2_rn(v0.w, n0.w - v0.w));
    ((uint4*)o)[0] = w;
    w.x = h2_as_u32(__floats2half2_rn(v1.x, n1.x - v1.x));
    w.y = h2_as_u32(__floats2half2_rn(v1.y, n1.y - v1.y));
    w.z = h2_as_u32(__floats2half2_rn(v1.z, n1.z - v1.z));
    w.w = h2_as_u32(__floats2half2_rn(v1.w, n1.w - v1.w));
    ((uint4*)o)[1] = w;
    w.x = h2_as_u32(__floats2half2_rn(v2.x, n2.x - v2.x));
    w.y = h2_as_u32(__floats2half2_rn(v2.y, n2.y - v2.y));
    w.z = h2_as_u32(__floats2half2_rn(v2.z, n2.z - v2.z));
    w.w = h2_as_u32(__floats2half2_rn(v2.w, n2.w - v2.w));
    ((uint4*)o)[2] = w;
    w.x = __float_as_uint(pv);
    w.y = __float_as_uint(pn - pv);
    w.z = 0u; w.w = 0u;
    ((uint4*)o)[3] = w;
}

// ---- main: 4 lanes/row, 64 rows/CTA, 8-step chunks, bulk-copy output ----
__global__ void __launch_bounds__(256) mlp_lookup(
    const int* __restrict__ aI, const int* __restrict__ bI, float* __restrict__ out)
{
    __shared__ __align__(16) unsigned char sdig[ROWS_CTA * 64];   // [row][t] pair index
    __shared__ __align__(16) float sdg[ROWS_CTA * SDG_RS];        // [row][s*10+d]
    __shared__ __align__(16) float scar[ROWS_CTA * SCAR_RS];      // [row][s*2+k]
    __shared__ int sflagA, sflagB;

    int tid = threadIdx.x;           // 256
    int lrow = tid >> 2;             // 0..63 (row within CTA)
    int q = tid & 3;                 // lane within 4-lane row group
    int lane = tid & 31;
    int rowbase = blockIdx.x * ROWS_CTA;

    // dtype sniff: int64 viewed as int32 has high words (odd indices) all zero
    if (tid < 32) {
        int v = aI[2 * tid + 1];
        unsigned m = __ballot_sync(0xffffffffu, v == 0);
        if (tid == 0) sflagA = (m == 0xffffffffu);
    } else if (tid < 64) {
        int l = tid - 32;
        int v = bI[2 * l + 1];
        unsigned m = __ballot_sync(0xffffffffu, v == 0);
        if (l == 0) sflagB = (m == 0xffffffffu);
    }
    __syncthreads();
    bool f64a = sflagA != 0, f64b = sflagB != 0;

    // load + transpose this CTA's digits into smem (64 rows x 64 t)
    #pragma unroll
    for (int kk = 0; kk < 16; kk++) {
        int i = tid + kk * 256;      // 0..4095
        int r = i >> 6, t = i & 63;
        size_t idx = (size_t)(rowbase + r) * NL + t;
        int av = f64a ? aI[2 * idx] : aI[idx];
        int bv = f64b ? bI[2 * idx] : bI[idx];
        sdig[r * 64 + t] = (unsigned char)(av * 10 + bv);
    }
    __syncthreads();

    // per-thread store routing (loop-invariant): q0/q1/q2 store, q3 is the u lane
    float* digrow = sdg + lrow * SDG_RS;
    float* carrow = scar + lrow * SCAR_RS;
    float *p1, *p2; int st1, st2;
    if (q == 0)      { p1 = digrow;     st1 = 10; p2 = digrow + 2; st2 = 10; }
    else if (q == 1) { p1 = digrow + 4; st1 = 10; p2 = digrow + 6; st2 = 10; }
    else if (q == 2) { p1 = digrow + 8; st1 = 10; p2 = carrow;     st2 = 2;  }
    else             { p1 = digrow;     st1 = 0;  p2 = digrow;     st2 = 0;  }
    bool doStore = (q < 3);
    int psrc = lane | 3;             // lane holding u_next (q==3) in this 4-lane group

    // bulk-copy routing (tid < 128 issues one copy per chunk)
    float* bdst0 = 0; const float* bsrc = 0; unsigned bbytes = 0; int bstep = 0;
    float* outc_base = out + (size_t)NB * NL * 10;
    if (tid < ROWS_CTA) {
        bdst0 = out + (size_t)(rowbase + tid) * (NL * 10);
        bsrc = sdg + tid * SDG_RS;
        bbytes = 320; bstep = 80;
    } else if (tid < 2 * ROWS_CTA) {
        int r = tid - ROWS_CTA;
        bdst0 = outc_base + (size_t)(rowbase + r) * (NL * 2);
        bsrc = scar + r * SCAR_RS;
        bbytes = 64; bstep = 16;
    }

    const unsigned int* T = g_tab16;
    float u = 0.f;   // scaled recursion state u = p * GRID_P; t=0 carry = [1,0] <=> u = 0

    #pragma unroll 1
    for (int c = 0; c < 8; c++) {
        if (c > 0) {
            if (tid < 2 * ROWS_CTA) bulk_wait_read0();   // staging free for reuse
            __syncthreads();
        }

        // 8 pair-bytes for this chunk in one LDS.64
        ull w8 = *(const ull*)(sdig + lrow * 64 + c * 8);

        #pragma unroll
        for (int s = 0; s < 8; s++) {
            int pr = (int)((w8 >> (8 * s)) & 255u);

            // k via F2I; f via parallel F2F.RZI (off the address chain)
            int k = (int)u;
            float fl = truncf(u);
            k = min(k, GRID_P - 1);
            fl = fminf(fl, (float)(GRID_P - 1));
            float f = u - fl;

            uint4 w = *(const uint4*)(T + (((size_t)(pr * NPTS + k)) << 4) + 4 * q);
            float r0, r1, r2, r3;
            if (q == 3) {
                r0 = fmaf(f, __uint_as_float(w.y), __uint_as_float(w.x));  // u_next
                r1 = 0.f; r2 = 0.f; r3 = 0.f;
            } else {
                float2 a0 = __half22float2(u32_as_h2(w.x));
                float2 a1 = __half22float2(u32_as_h2(w.y));
                float2 a2 = __half22float2(u32_as_h2(w.z));
                float2 a3 = __half22float2(u32_as_h2(w.w));
                r0 = fmaf(f, a0.y, a0.x);
                r1 = fmaf(f, a1.y, a1.x);
                r2 = fmaf(f, a2.y, a2.x);
                r3 = fmaf(f, a3.y, a3.x);
            }

            if (doStore) {
                *(float2*)(p1 + s * st1) = make_float2(r0, r1);
                *(float2*)(p2 + s * st2) = make_float2(r2, r3);
            }

            // q==3 r0 = u_next; broadcast within 4-lane group
            u = __shfl_sync(0xffffffffu, r0, psrc, 32);
        }
        __syncthreads();

        // DMA this chunk's staging out (smem -> gmem, bypassing the register path)
        if (tid < 2 * ROWS_CTA) {
            fence_async_shared();
            bulk_s2g(bdst0 + (size_t)c * bstep, bsrc, bbytes);
            bulk_commit();
        }
    }

    // writes must be complete/visible before the grid exits
    if (tid < 2 * ROWS_CTA) bulk_wait0();
}

extern "C" void kernel_launch(void* const* d_in, const int* in_sizes, int n_in,
                              void* d_out, int out_size) {
    const int*   a  = (const int*)d_in[0];
    const int*   b  = (const int*)d_in[1];
    const float* Ea = (const float*)d_in[2];
    const float* Eb = (const float*)d_in[3];
    const float* W1 = (const float*)d_in[4];
    const float* b1 = (const float*)d_in[5];
    const float* W2 = (const float*)d_in[6];
    const float* b2 = (const float*)d_in[7];
    const float* Wd = (const float*)d_in[8];
    const float* bd = (const float*)d_in[9];
    const float* Wc = (const float*)d_in[10];
    const float* bc = (const float*)d_in[11];

    build_vals<<<(NPAIR * NPTS + 255) / 256, 256>>>(Ea, Eb, W1, b1, W2, b2, Wd, bd, Wc, bc);
    finalize_tab<<<(NPAIR * NPTS + 255) / 256, 256>>>();
    mlp_lookup<<<NB / ROWS_CTA, 256>>>(a, b, (float*)d_out);
}